// round 2
// baseline (speedup 1.0000x reference)
#include <cuda_runtime.h>
#include <math.h>

#define NE   8
#define HD   2048
#define ID   1024
#define NT   8192
#define TOPK 2
#define MAXP (NT * TOPK)   // 16384 token-expert pairs

#define BM 128
#define BN 64
#define BK 16

// ---- scratch (device globals; no allocation in kernel_launch) ----
__device__ int   g_cnt[NE];
__device__ int   g_pair[NE * MAXP];                 // pair id = t*TOPK + k
__device__ float g_act[(size_t)MAXP * ID];          // 64 MB activation scratch

// ---------------------------------------------------------------------------
__global__ void k_zero_counts() {
    if (threadIdx.x < NE) g_cnt[threadIdx.x] = 0;
}

__global__ void k_route(const int* __restrict__ sel) {
    int p = blockIdx.x * blockDim.x + threadIdx.x;
    if (p < MAXP) {
        int e = sel[p];
        int pos = atomicAdd(&g_cnt[e], 1);
        g_pair[e * MAXP + pos] = p;
    }
}

// ---------------------------------------------------------------------------
// Fused gate+up GEMM with gathered A rows, gelu(tanh)*up epilogue.
// C_g[m,n] = sum_h x[tok_m, h] * gate_w[e, h, n]   (and same for up_w)
// act[pair_m, n] = gelu(C_g) * C_u
__global__ __launch_bounds__(256, 2) void k_gateup(
    const float* __restrict__ x,
    const float* __restrict__ gate_w,
    const float* __restrict__ up_w)
{
    const int e = blockIdx.z;
    const int cnt = g_cnt[e];
    const int row0 = blockIdx.y * BM;
    if (row0 >= cnt) return;
    const int col0 = blockIdx.x * BN;

    __shared__ float As[BK][BM];
    __shared__ float Bg[BK][BN];
    __shared__ float Bu[BK][BN];
    __shared__ int   sPair[BM];

    const int tid = threadIdx.x;
    if (tid < BM) {
        int pos = row0 + tid;
        sPair[tid] = (pos < cnt) ? g_pair[e * MAXP + pos] : -1;
    }
    __syncthreads();

    float accg[8][4] = {};
    float accu[8][4] = {};

    const float* gw = gate_w + (size_t)e * HD * ID;
    const float* uw = up_w   + (size_t)e * HD * ID;

    const int tx = tid & 15;   // n direction
    const int ty = tid >> 4;   // m direction
    const int m0 = ty * 8, n0 = tx * 4;

    // B-load mapping: one float4 per thread per matrix
    const int bk  = tid >> 4;          // 0..15
    const int bn4 = (tid & 15) * 4;    // 0..60

    for (int kk = 0; kk < HD; kk += BK) {
        // A tile: 128 rows x 16 k -> 512 float4 slots, 2 per thread
        #pragma unroll
        for (int it = 0; it < 2; ++it) {
            int s    = tid + it * 256;
            int arow = s >> 2;
            int k4   = (s & 3) * 4;
            int pr   = sPair[arow];
            float4 v = make_float4(0.f, 0.f, 0.f, 0.f);
            if (pr >= 0) {
                int tok = pr >> 1;   // TOPK == 2
                v = *(const float4*)(x + (size_t)tok * HD + kk + k4);
            }
            As[k4 + 0][arow] = v.x;
            As[k4 + 1][arow] = v.y;
            As[k4 + 2][arow] = v.z;
            As[k4 + 3][arow] = v.w;
        }
        // B tiles
        {
            size_t boff = (size_t)(kk + bk) * ID + col0 + bn4;
            *(float4*)&Bg[bk][bn4] = *(const float4*)(gw + boff);
            *(float4*)&Bu[bk][bn4] = *(const float4*)(uw + boff);
        }
        __syncthreads();

        #pragma unroll
        for (int k = 0; k < BK; ++k) {
            float4 a0 = *(float4*)&As[k][m0];
            float4 a1 = *(float4*)&As[k][m0 + 4];
            float4 bg = *(float4*)&Bg[k][n0];
            float4 bu = *(float4*)&Bu[k][n0];
            float a[8] = {a0.x, a0.y, a0.z, a0.w, a1.x, a1.y, a1.z, a1.w};
            float vg[4] = {bg.x, bg.y, bg.z, bg.w};
            float vu[4] = {bu.x, bu.y, bu.z, bu.w};
            #pragma unroll
            for (int j = 0; j < 8; ++j)
                #pragma unroll
                for (int i = 0; i < 4; ++i) {
                    accg[j][i] += a[j] * vg[i];
                    accu[j][i] += a[j] * vu[i];
                }
        }
        __syncthreads();
    }

    // epilogue: gelu (tanh approx, via exp) * up -> g_act[pair, col]
    #pragma unroll
    for (int j = 0; j < 8; ++j) {
        int pr = sPair[m0 + j];
        if (pr < 0) continue;
        float4 outv;
        #pragma unroll
        for (int i = 0; i < 4; ++i) {
            float gv = accg[j][i];
            float t  = gv + 0.044715f * gv * gv * gv;
            float z  = 1.5957691216057308f * t;      // 2 * 0.79788456 * t
            // tanh(z/.. ) identity: tanh(a) = 1 - 2/(exp(2a)+1), here 2a = z
            float th = 1.0f - 2.0f / (__expf(z) + 1.0f);
            float ge = 0.5f * gv * (1.0f + th);
            ((float*)&outv)[i] = ge * accu[j][i];
        }
        *(float4*)(g_act + (size_t)pr * ID + col0 + n0) = outv;
    }
}

// ---------------------------------------------------------------------------
// Down-proj GEMM: C[m,h] = sum_i act[pair_m, i] * down_w[e, i, h]
// out[tok_m, h] += rw[pair_m] * C[m,h]   (exactly 2 atomic contributions/elem)
__global__ __launch_bounds__(256, 2) void k_down(
    const float* __restrict__ down_w,
    const float* __restrict__ rw,
    float* __restrict__ out)
{
    const int e = blockIdx.z;
    const int cnt = g_cnt[e];
    const int row0 = blockIdx.y * BM;
    if (row0 >= cnt) return;
    const int col0 = blockIdx.x * BN;

    __shared__ float As[BK][BM];
    __shared__ float Bs[BK][BN];
    __shared__ int   sPair[BM];

    const int tid = threadIdx.x;
    if (tid < BM) {
        int pos = row0 + tid;
        sPair[tid] = (pos < cnt) ? g_pair[e * MAXP + pos] : -1;
    }
    __syncthreads();

    float acc[8][4] = {};
    const float* dw = down_w + (size_t)e * ID * HD;

    const int tx = tid & 15;
    const int ty = tid >> 4;
    const int m0 = ty * 8, n0 = tx * 4;
    const int bk  = tid >> 4;
    const int bn4 = (tid & 15) * 4;

    for (int kk = 0; kk < ID; kk += BK) {
        #pragma unroll
        for (int it = 0; it < 2; ++it) {
            int s    = tid + it * 256;
            int arow = s >> 2;
            int k4   = (s & 3) * 4;
            int pr   = sPair[arow];
            float4 v = make_float4(0.f, 0.f, 0.f, 0.f);
            if (pr >= 0)
                v = *(const float4*)(g_act + (size_t)pr * ID + kk + k4);
            As[k4 + 0][arow] = v.x;
            As[k4 + 1][arow] = v.y;
            As[k4 + 2][arow] = v.z;
            As[k4 + 3][arow] = v.w;
        }
        *(float4*)&Bs[bk][bn4] =
            *(const float4*)(dw + (size_t)(kk + bk) * HD + col0 + bn4);
        __syncthreads();

        #pragma unroll
        for (int k = 0; k < BK; ++k) {
            float4 a0 = *(float4*)&As[k][m0];
            float4 a1 = *(float4*)&As[k][m0 + 4];
            float4 b  = *(float4*)&Bs[k][n0];
            float a[8] = {a0.x, a0.y, a0.z, a0.w, a1.x, a1.y, a1.z, a1.w};
            float vb[4] = {b.x, b.y, b.z, b.w};
            #pragma unroll
            for (int j = 0; j < 8; ++j)
                #pragma unroll
                for (int i = 0; i < 4; ++i)
                    acc[j][i] += a[j] * vb[i];
        }
        __syncthreads();
    }

    #pragma unroll
    for (int j = 0; j < 8; ++j) {
        int pr = sPair[m0 + j];
        if (pr < 0) continue;
        int tok = pr >> 1;
        float w = rw[pr];
        float* o = out + (size_t)tok * HD + col0 + n0;
        #pragma unroll
        for (int i = 0; i < 4; ++i)
            atomicAdd(o + i, w * acc[j][i]);
    }
}

// ---------------------------------------------------------------------------
extern "C" void kernel_launch(void* const* d_in, const int* in_sizes, int n_in,
                              void* d_out, int out_size)
{
    const float* x      = (const float*)d_in[0];
    const int*   sel    = (const int*)  d_in[1];
    const float* rw     = (const float*)d_in[2];
    const float* gate_w = (const float*)d_in[3];
    const float* up_w   = (const float*)d_in[4];
    const float* down_w = (const float*)d_in[5];
    float* out = (float*)d_out;

    cudaMemsetAsync(out, 0, (size_t)NT * HD * sizeof(float));
    k_zero_counts<<<1, 32>>>();
    k_route<<<MAXP / 256, 256>>>(sel);

    dim3 g1(ID / BN, MAXP / BM, NE);   // 16 x 128 x 8 (early-exit beyond cnt)
    k_gateup<<<g1, 256>>>(x, gate_w, up_w);

    dim3 g2(HD / BN, MAXP / BM, NE);   // 32 x 128 x 8
    k_down<<<g2, 256>>>(down_w, rw, out);
}

// round 7
// speedup vs baseline: 2.1578x; 2.1578x over previous
#include <cuda_runtime.h>
#include <cuda_bf16.h>
#include <cstdint>
#include <math.h>

#define NE   8
#define HD   2048
#define ID   1024
#define NT   8192
#define TOPK 2
#define MAXP (NT * TOPK)

// ---- scratch (device globals) ----
__device__ int            g_cnt[NE];
__device__ int            g_pair[NE * MAXP];
__device__ __nv_bfloat16  g_act_h[(size_t)MAXP * ID];   // 32 MB
__device__ __nv_bfloat16  g_act_l[(size_t)MAXP * ID];   // 32 MB
__device__ float          g_ds[(size_t)MAXP * HD];      // 128 MB

// ============================ helpers ============================
__device__ __forceinline__ uint32_t smem_to_u32(const void* p) {
    uint32_t a;
    asm("{ .reg .u64 t; cvta.to.shared.u64 t, %1; cvt.u32.u64 %0, t; }" : "=r"(a) : "l"(p));
    return a;
}
__device__ __forceinline__ void ldm_x4(uint32_t* r, uint32_t a) {
    asm volatile("ldmatrix.sync.aligned.m8n8.x4.shared.b16 {%0,%1,%2,%3}, [%4];"
                 : "=r"(r[0]), "=r"(r[1]), "=r"(r[2]), "=r"(r[3]) : "r"(a));
}
__device__ __forceinline__ void ldm_x4_t(uint32_t* r, uint32_t a) {
    asm volatile("ldmatrix.sync.aligned.m8n8.x4.trans.shared.b16 {%0,%1,%2,%3}, [%4];"
                 : "=r"(r[0]), "=r"(r[1]), "=r"(r[2]), "=r"(r[3]) : "r"(a));
}
__device__ __forceinline__ void mma16816(float* c, const uint32_t* a, uint32_t b0, uint32_t b1) {
    asm volatile("mma.sync.aligned.m16n8k16.row.col.f32.bf16.bf16.f32 "
                 "{%0,%1,%2,%3}, {%4,%5,%6,%7}, {%8,%9}, {%0,%1,%2,%3};"
                 : "+f"(c[0]), "+f"(c[1]), "+f"(c[2]), "+f"(c[3])
                 : "r"(a[0]), "r"(a[1]), "r"(a[2]), "r"(a[3]), "r"(b0), "r"(b1));
}
__device__ __forceinline__ uint32_t pk(__nv_bfloat16 a, __nv_bfloat16 b) {
    __nv_bfloat162 t(a, b);
    return *reinterpret_cast<uint32_t*>(&t);
}
__device__ __forceinline__ void split4(float4 v, uint2& H, uint2& L) {
    __nv_bfloat16 h0 = __float2bfloat16(v.x), h1 = __float2bfloat16(v.y);
    __nv_bfloat16 h2 = __float2bfloat16(v.z), h3 = __float2bfloat16(v.w);
    __nv_bfloat16 l0 = __float2bfloat16(v.x - __bfloat162float(h0));
    __nv_bfloat16 l1 = __float2bfloat16(v.y - __bfloat162float(h1));
    __nv_bfloat16 l2 = __float2bfloat16(v.z - __bfloat162float(h2));
    __nv_bfloat16 l3 = __float2bfloat16(v.w - __bfloat162float(h3));
    H.x = pk(h0, h1); H.y = pk(h2, h3);
    L.x = pk(l0, l1); L.y = pk(l2, l3);
}
__device__ __forceinline__ float gelu_tanh(float gv) {
    float t  = gv + 0.044715f * gv * gv * gv;
    float z  = 1.5957691216057308f * t;
    float th = 1.0f - 2.0f / (__expf(z) + 1.0f);
    return 0.5f * gv * (1.0f + th);
}

#define SA 40    // A smem stride (bf16 elems): 32 + 8 pad
#define SB 136   // B smem stride: 128 + 8 pad

// ============================ routing ============================
__global__ void k_zero_counts() { if (threadIdx.x < NE) g_cnt[threadIdx.x] = 0; }

__global__ void k_route(const int* __restrict__ sel) {
    int p = blockIdx.x * blockDim.x + threadIdx.x;
    if (p < MAXP) {
        int e = sel[p];
        int pos = atomicAdd(&g_cnt[e], 1);
        g_pair[e * MAXP + pos] = p;
    }
}

// ============================ gate+up ============================
// CTA: 128 pairs x (64 gate cols + 64 up cols), K = HD in 32-chunks.
// Warp grid 4x4: warp (wm, wn) covers m = wm*32..+32,
// gate cols wn*16..+16 and up cols 64+wn*16..+16 (same A reuse, paired epilogue).
__global__ __launch_bounds__(512, 1)
void k_gateup(const float* __restrict__ x,
              const float* __restrict__ gate_w,
              const float* __restrict__ up_w,
              const float* __restrict__ rw)
{
    const int e = blockIdx.z;
    const int cnt = g_cnt[e];
    const int row0 = blockIdx.y * 128;
    if (row0 >= cnt) return;
    const int cb = blockIdx.x;                 // 64-col block of ID: 0..15

    __shared__ __align__(16) __nv_bfloat16 As_h[128][SA];
    __shared__ __align__(16) __nv_bfloat16 As_l[128][SA];
    __shared__ __align__(16) __nv_bfloat16 Bs_h[32][SB];
    __shared__ __align__(16) __nv_bfloat16 Bs_l[32][SB];
    __shared__ int sPair[128];

    const int tid = threadIdx.x, wid = tid >> 5, lane = tid & 31;
    const int wm = wid >> 2, wn = wid & 3;

    if (tid < 128) {
        int pos = row0 + tid;
        sPair[tid] = (pos < cnt) ? g_pair[e * MAXP + pos] : -1;
    }
    __syncthreads();

    const uint32_t uAh = smem_to_u32(&As_h[0][0]);
    const uint32_t uAl = smem_to_u32(&As_l[0][0]);
    const uint32_t uBh = smem_to_u32(&Bs_h[0][0]);
    const uint32_t uBl = smem_to_u32(&Bs_l[0][0]);

    const float* gw = gate_w + (size_t)e * HD * ID;
    const float* uw = up_w   + (size_t)e * HD * ID;

    float acc[2][2][2][4];
    #pragma unroll
    for (int i = 0; i < 2; ++i)
        #pragma unroll
        for (int j = 0; j < 2; ++j)
            #pragma unroll
            for (int s = 0; s < 2; ++s)
                #pragma unroll
                for (int q = 0; q < 4; ++q) acc[i][j][s][q] = 0.f;

    float4 ar[2], br[2];
    // prologue: load chunk 0
    #pragma unroll
    for (int it = 0; it < 2; ++it) {
        int s = tid + it * 512;
        { int r = s >> 3, k4 = (s & 7) << 2; int pr = sPair[r];
          ar[it] = (pr >= 0) ? *(const float4*)(x + (size_t)(pr >> 1) * HD + k4)
                             : make_float4(0.f, 0.f, 0.f, 0.f); }
        { int mat = s >> 9, rem = s & 511; int kr = rem >> 4, n4 = (rem & 15) << 2;
          const float* w = mat ? uw : gw;
          br[it] = *(const float4*)(w + (size_t)kr * ID + cb * 64 + n4); }
    }

    for (int ck = 0; ck < HD / 32; ++ck) {
        // STS current chunk
        #pragma unroll
        for (int it = 0; it < 2; ++it) {
            int s = tid + it * 512;
            { int r = s >> 3, k4 = (s & 7) << 2;
              uint2 H, L; split4(ar[it], H, L);
              *(uint2*)&As_h[r][k4] = H; *(uint2*)&As_l[r][k4] = L; }
            { int mat = s >> 9, rem = s & 511; int kr = rem >> 4, n4 = (rem & 15) << 2;
              uint2 H, L; split4(br[it], H, L);
              *(uint2*)&Bs_h[kr][mat * 64 + n4] = H;
              *(uint2*)&Bs_l[kr][mat * 64 + n4] = L; }
        }
        __syncthreads();

        // prefetch next chunk
        if (ck + 1 < HD / 32) {
            int kk = (ck + 1) * 32;
            #pragma unroll
            for (int it = 0; it < 2; ++it) {
                int s = tid + it * 512;
                { int r = s >> 3, k4 = (s & 7) << 2; int pr = sPair[r];
                  ar[it] = (pr >= 0) ? *(const float4*)(x + (size_t)(pr >> 1) * HD + kk + k4)
                                     : make_float4(0.f, 0.f, 0.f, 0.f); }
                { int mat = s >> 9, rem = s & 511; int kr = rem >> 4, n4 = (rem & 15) << 2;
                  const float* w = mat ? uw : gw;
                  br[it] = *(const float4*)(w + (size_t)(kk + kr) * ID + cb * 64 + n4); }
            }
        }

        // compute from smem
        #pragma unroll
        for (int ks = 0; ks < 2; ++ks) {
            uint32_t ah[2][4], al[2][4];
            #pragma unroll
            for (int mt = 0; mt < 2; ++mt) {
                uint32_t off = (uint32_t)((wm * 32 + mt * 16 + (lane & 15)) * SA
                                          + ks * 16 + ((lane >> 4) << 3)) * 2;
                ldm_x4(ah[mt], uAh + off);
                ldm_x4(al[mt], uAl + off);
            }
            uint32_t bg[2][4], bu[2][4];
            {
                uint32_t brow = (uint32_t)(ks * 16 + (lane & 15));
                uint32_t co   = (uint32_t)((lane >> 4) << 3);
                uint32_t offg = (brow * SB + wn * 16 + co) * 2;
                uint32_t offu = (brow * SB + 64 + wn * 16 + co) * 2;
                ldm_x4_t(bg[0], uBh + offg); ldm_x4_t(bg[1], uBl + offg);
                ldm_x4_t(bu[0], uBh + offu); ldm_x4_t(bu[1], uBl + offu);
            }
            #pragma unroll
            for (int mt = 0; mt < 2; ++mt)
                #pragma unroll
                for (int s = 0; s < 2; ++s) {
                    mma16816(acc[mt][0][s], ah[mt], bg[0][2 * s], bg[0][2 * s + 1]);
                    mma16816(acc[mt][0][s], ah[mt], bg[1][2 * s], bg[1][2 * s + 1]);
                    mma16816(acc[mt][0][s], al[mt], bg[0][2 * s], bg[0][2 * s + 1]);
                    mma16816(acc[mt][1][s], ah[mt], bu[0][2 * s], bu[0][2 * s + 1]);
                    mma16816(acc[mt][1][s], ah[mt], bu[1][2 * s], bu[1][2 * s + 1]);
                    mma16816(acc[mt][1][s], al[mt], bu[0][2 * s], bu[0][2 * s + 1]);
                }
        }
        __syncthreads();
    }

    // epilogue: act = rw * gelu(gate) * up -> bf16 hi/lo scratch
    #pragma unroll
    for (int mt = 0; mt < 2; ++mt)
        #pragma unroll
        for (int s = 0; s < 2; ++s) {
            int c = cb * 64 + wn * 16 + s * 8 + (lane & 3) * 2;
            #pragma unroll
            for (int half = 0; half < 2; ++half) {
                int r = wm * 32 + mt * 16 + (lane >> 2) + half * 8;
                int pr = sPair[r];
                if (pr < 0) continue;
                float wgt = rw[pr];
                float g0 = acc[mt][0][s][half * 2],     g1 = acc[mt][0][s][half * 2 + 1];
                float u0 = acc[mt][1][s][half * 2],     u1 = acc[mt][1][s][half * 2 + 1];
                float o0 = wgt * gelu_tanh(g0) * u0;
                float o1 = wgt * gelu_tanh(g1) * u1;
                __nv_bfloat16 h0 = __float2bfloat16(o0), h1 = __float2bfloat16(o1);
                __nv_bfloat16 l0 = __float2bfloat16(o0 - __bfloat162float(h0));
                __nv_bfloat16 l1 = __float2bfloat16(o1 - __bfloat162float(h1));
                size_t base = (size_t)pr * ID + c;
                *(uint32_t*)(g_act_h + base) = pk(h0, h1);
                *(uint32_t*)(g_act_l + base) = pk(l0, l1);
            }
        }
}

// ============================ down ============================
// CTA: 128 pairs x 128 hidden cols, K = ID in 32-chunks. A = bf16 hi/lo scratch.
__global__ __launch_bounds__(512, 1)
void k_down(const float* __restrict__ down_w)
{
    const int e = blockIdx.z;
    const int cnt = g_cnt[e];
    const int row0 = blockIdx.y * 128;
    if (row0 >= cnt) return;
    const int cb = blockIdx.x;                 // 128-col block of HD: 0..15

    __shared__ __align__(16) __nv_bfloat16 As_h[128][SA];
    __shared__ __align__(16) __nv_bfloat16 As_l[128][SA];
    __shared__ __align__(16) __nv_bfloat16 Bs_h[32][SB];
    __shared__ __align__(16) __nv_bfloat16 Bs_l[32][SB];
    __shared__ int sPair[128];

    const int tid = threadIdx.x, wid = tid >> 5, lane = tid & 31;
    const int wm = wid >> 2, wn = wid & 3;

    if (tid < 128) {
        int pos = row0 + tid;
        sPair[tid] = (pos < cnt) ? g_pair[e * MAXP + pos] : -1;
    }
    __syncthreads();

    const uint32_t uAh = smem_to_u32(&As_h[0][0]);
    const uint32_t uAl = smem_to_u32(&As_l[0][0]);
    const uint32_t uBh = smem_to_u32(&Bs_h[0][0]);
    const uint32_t uBl = smem_to_u32(&Bs_l[0][0]);

    const float* dw = down_w + (size_t)e * ID * HD;

    float acc[2][4][4];
    #pragma unroll
    for (int i = 0; i < 2; ++i)
        #pragma unroll
        for (int j = 0; j < 4; ++j)
            #pragma unroll
            for (int q = 0; q < 4; ++q) acc[i][j][q] = 0.f;

    uint2 arh[2], arl[2];
    float4 br[2];
    #pragma unroll
    for (int it = 0; it < 2; ++it) {
        int s = tid + it * 512;
        { int r = s >> 3, c4 = (s & 7) << 2; int pr = sPair[r];
          if (pr >= 0) {
              arh[it] = *(const uint2*)(g_act_h + (size_t)pr * ID + c4);
              arl[it] = *(const uint2*)(g_act_l + (size_t)pr * ID + c4);
          } else { arh[it] = make_uint2(0u, 0u); arl[it] = make_uint2(0u, 0u); } }
        { int kr = s >> 5, n4 = (s & 31) << 2;
          br[it] = *(const float4*)(dw + (size_t)kr * HD + cb * 128 + n4); }
    }

    for (int ck = 0; ck < ID / 32; ++ck) {
        #pragma unroll
        for (int it = 0; it < 2; ++it) {
            int s = tid + it * 512;
            { int r = s >> 3, c4 = (s & 7) << 2;
              *(uint2*)&As_h[r][c4] = arh[it];
              *(uint2*)&As_l[r][c4] = arl[it]; }
            { int kr = s >> 5, n4 = (s & 31) << 2;
              uint2 H, L; split4(br[it], H, L);
              *(uint2*)&Bs_h[kr][n4] = H;
              *(uint2*)&Bs_l[kr][n4] = L; }
        }
        __syncthreads();

        if (ck + 1 < ID / 32) {
            int kk = (ck + 1) * 32;
            #pragma unroll
            for (int it = 0; it < 2; ++it) {
                int s = tid + it * 512;
                { int r = s >> 3, c4 = (s & 7) << 2; int pr = sPair[r];
                  if (pr >= 0) {
                      arh[it] = *(const uint2*)(g_act_h + (size_t)pr * ID + kk + c4);
                      arl[it] = *(const uint2*)(g_act_l + (size_t)pr * ID + kk + c4);
                  } else { arh[it] = make_uint2(0u, 0u); arl[it] = make_uint2(0u, 0u); } }
                { int kr = s >> 5, n4 = (s & 31) << 2;
                  br[it] = *(const float4*)(dw + (size_t)(kk + kr) * HD + cb * 128 + n4); }
            }
        }

        #pragma unroll
        for (int ks = 0; ks < 2; ++ks) {
            uint32_t ah[2][4], al[2][4];
            #pragma unroll
            for (int mt = 0; mt < 2; ++mt) {
                uint32_t off = (uint32_t)((wm * 32 + mt * 16 + (lane & 15)) * SA
                                          + ks * 16 + ((lane >> 4) << 3)) * 2;
                ldm_x4(ah[mt], uAh + off);
                ldm_x4(al[mt], uAl + off);
            }
            uint32_t bh[2][4], bl[2][4];
            {
                uint32_t brow = (uint32_t)(ks * 16 + (lane & 15));
                uint32_t co   = (uint32_t)((lane >> 4) << 3);
                #pragma unroll
                for (int np = 0; np < 2; ++np) {
                    uint32_t off = (brow * SB + wn * 32 + np * 16 + co) * 2;
                    ldm_x4_t(bh[np], uBh + off);
                    ldm_x4_t(bl[np], uBl + off);
                }
            }
            #pragma unroll
            for (int mt = 0; mt < 2; ++mt)
                #pragma unroll
                for (int np = 0; np < 2; ++np)
                    #pragma unroll
                    for (int s = 0; s < 2; ++s) {
                        int j = np * 2 + s;
                        mma16816(acc[mt][j], ah[mt], bh[np][2 * s], bh[np][2 * s + 1]);
                        mma16816(acc[mt][j], ah[mt], bl[np][2 * s], bl[np][2 * s + 1]);
                        mma16816(acc[mt][j], al[mt], bh[np][2 * s], bh[np][2 * s + 1]);
                    }
        }
        __syncthreads();
    }

    // epilogue: per-pair fp32 scratch
    #pragma unroll
    for (int mt = 0; mt < 2; ++mt)
        #pragma unroll
        for (int j = 0; j < 4; ++j) {
            int c = cb * 128 + wn * 32 + j * 8 + (lane & 3) * 2;
            #pragma unroll
            for (int half = 0; half < 2; ++half) {
                int r = wm * 32 + mt * 16 + (lane >> 2) + half * 8;
                int pr = sPair[r];
                if (pr < 0) continue;
                float2 v = make_float2(acc[mt][j][half * 2], acc[mt][j][half * 2 + 1]);
                *(float2*)(g_ds + (size_t)pr * HD + c) = v;
            }
        }
}

// ============================ combine ============================
__global__ void k_combine(float* __restrict__ out) {
    int idx = blockIdx.x * blockDim.x + threadIdx.x;   // NT*HD/4 float4s
    int t  = idx >> 9;
    int c4 = idx & 511;
    const float4* s4 = (const float4*)g_ds;
    float4 a = s4[(size_t)(2 * t) * 512 + c4];
    float4 b = s4[(size_t)(2 * t + 1) * 512 + c4];
    ((float4*)out)[idx] = make_float4(a.x + b.x, a.y + b.y, a.z + b.z, a.w + b.w);
}

// ============================ host ============================
extern "C" void kernel_launch(void* const* d_in, const int* in_sizes, int n_in,
                              void* d_out, int out_size)
{
    const float* x      = (const float*)d_in[0];
    const int*   sel    = (const int*)  d_in[1];
    const float* rw     = (const float*)d_in[2];
    const float* gate_w = (const float*)d_in[3];
    const float* up_w   = (const float*)d_in[4];
    const float* down_w = (const float*)d_in[5];
    float* out = (float*)d_out;

    k_zero_counts<<<1, 32>>>();
    k_route<<<MAXP / 256, 256>>>(sel);

    dim3 g1(ID / 64, MAXP / 128, NE);    // 16 x 128 x 8
    k_gateup<<<g1, 512>>>(x, gate_w, up_w, rw);

    dim3 g2(HD / 128, MAXP / 128, NE);   // 16 x 128 x 8
    k_down<<<g2, 512>>>(down_w);

    k_combine<<<(NT * HD / 4) / 256, 256>>>(out);
}